// round 3
// baseline (speedup 1.0000x reference)
#include <cuda_runtime.h>

// ---------------- problem constants ----------------
#define BB      64          // batch
#define CC      256         // channels
#define HWX     3136        // 56*56
#define G       4           // whitening groups
#define NCH     64          // channels per group
#define MTOT    (BB*HWX)    // 200704 samples per group
#define TS      112         // samples per tile (divides 3136: 28 chunks)
#define CHUNKS  (HWX/TS)    // 28
#define TILESG  (BB*CHUNKS) // 1792 tiles per group
#define NBLK    74          // blocks per group (grid = 296 = 2 per SM)
#define EPSV    1e-5f
#define NS_T    5

// ---------------- device scratch (no allocations allowed) ----------------
__device__ float g_S2[G][NCH][NCH];   // sum of x x^T
__device__ float g_sum[G][NCH];       // sum of x
__device__ float g_wmT[G][NCH*NCH];   // folded whitening matrix, layout [d][c]
__device__ float g_beta[G][NCH];      // folded per-channel offset

// ---------------- zero scratch ----------------
__global__ void zero_kernel() {
    int i = blockIdx.x * blockDim.x + threadIdx.x;
    float* p = &g_S2[0][0][0];
    if (i < G * NCH * NCH) p[i] = 0.0f;
    if (i < G * NCH) (&g_sum[0][0])[i] = 0.0f;
}

// ---------------- phase 1: covariance raw moments ----------------
// grid = G*NBLK, block = 256. Each block: register-resident 4x4 micro-tile of
// the 64x64 S2 accumulator, looped over its share of 112-sample tiles, one
// atomic flush at the end.
__global__ __launch_bounds__(256) void cov_kernel(const float* __restrict__ x) {
    __shared__ float st[TS][68];      // transposed tile [s][c], pad 68 (16B-mult)

    const int gi  = blockIdx.x / NBLK;
    const int blk = blockIdx.x % NBLK;
    const int tid = threadIdx.x;
    const int ig  = tid >> 4;         // 0..15 -> rows ig*4..ig*4+3
    const int jg  = tid & 15;         // 0..15 -> cols jg*4..jg*4+3

    float acc[4][4] = {};
    float sacc[4]   = {0.f, 0.f, 0.f, 0.f};

    const float* xg = x + (size_t)gi * NCH * HWX;

    for (int t = blk; t < TILESG; t += NBLK) {
        const int bb = t / CHUNKS;
        const int cs = (t % CHUNKS) * TS;
        const float* base = xg + (size_t)bb * CC * HWX + cs;

        __syncthreads();   // previous tile fully consumed
        // load 64x112 floats = 1792 float4, 7 per thread, coalesced rows
        #pragma unroll
        for (int i = 0; i < 7; i++) {
            int idx = tid + 256 * i;
            int c   = idx / 28;
            int s4  = (idx % 28) * 4;
            float4 v = *reinterpret_cast<const float4*>(base + c * HWX + s4);
            st[s4 + 0][c] = v.x;
            st[s4 + 1][c] = v.y;
            st[s4 + 2][c] = v.z;
            st[s4 + 3][c] = v.w;
        }
        __syncthreads();

        #pragma unroll 4
        for (int k = 0; k < TS; k++) {
            float4 a = *reinterpret_cast<const float4*>(&st[k][ig * 4]);
            float4 b = *reinterpret_cast<const float4*>(&st[k][jg * 4]);
            float av[4] = {a.x, a.y, a.z, a.w};
            float bv[4] = {b.x, b.y, b.z, b.w};
            #pragma unroll
            for (int r = 0; r < 4; r++)
                #pragma unroll
                for (int q = 0; q < 4; q++)
                    acc[r][q] += av[r] * bv[q];
            if (ig == 0) {            // warp-0 lanes also collect channel sums
                sacc[0] += bv[0]; sacc[1] += bv[1];
                sacc[2] += bv[2]; sacc[3] += bv[3];
            }
        }
    }

    #pragma unroll
    for (int r = 0; r < 4; r++)
        #pragma unroll
        for (int q = 0; q < 4; q++)
            atomicAdd(&g_S2[gi][ig * 4 + r][jg * 4 + q], acc[r][q]);
    if (ig == 0) {
        #pragma unroll
        for (int q = 0; q < 4; q++)
            atomicAdd(&g_sum[gi][jg * 4 + q], sacc[q]);
    }
}

// ---------------- phase 2: Newton-Schulz + folding ----------------
// One block per group, 256 threads, dynamic smem: 4 matrices [64][65] + mean.
__device__ __forceinline__ void mm64(float* O, const float* A, const float* B) {
    const int r  = threadIdx.x >> 2;         // 0..63
    const int cb = (threadIdx.x & 3) << 4;   // 0,16,32,48
    float acc[16] = {};
    for (int k = 0; k < 64; k++) {
        float a = A[r * 65 + k];
        #pragma unroll
        for (int j = 0; j < 16; j++)
            acc[j] += a * B[k * 65 + cb + j];
    }
    #pragma unroll
    for (int j = 0; j < 16; j++)
        O[r * 65 + cb + j] = acc[j];
    __syncthreads();
}

__global__ __launch_bounds__(256) void ns_kernel(const float* __restrict__ weight,
                                                 const float* __restrict__ bias) {
    extern __shared__ float sm[];
    float* Sn   = sm;
    float* P    = sm + 4160;
    float* T1   = sm + 8320;
    float* T2   = sm + 12480;
    float* mean = sm + 16640;    // 64
    float* misc = sm + 16704;    // scalars

    const int gi  = blockIdx.x;
    const int tid = threadIdx.x;
    const int r   = tid >> 2;
    const int cb  = (tid & 3) << 4;

    if (tid < 64) mean[tid] = g_sum[gi][tid] * (1.0f / MTOT);
    __syncthreads();

    // Sigma -> Sn (unscaled for now)
    #pragma unroll
    for (int j = 0; j < 16; j++) {
        int c = cb + j;
        float sig = g_S2[gi][r][c] * (1.0f / MTOT) - mean[r] * mean[c];
        if (r == c) sig += EPSV;
        Sn[r * 65 + c] = sig;
    }
    __syncthreads();

    // trace -> rTr
    if (tid < 32) {
        float ts = Sn[tid * 65 + tid] + Sn[(tid + 32) * 65 + (tid + 32)];
        #pragma unroll
        for (int o = 16; o; o >>= 1) ts += __shfl_xor_sync(0xffffffffu, ts, o);
        if (tid == 0) misc[0] = 1.0f / ts;
    }
    __syncthreads();
    const float rTr = misc[0];

    // Sn *= rTr ; P = I
    #pragma unroll
    for (int j = 0; j < 16; j++) {
        int c = cb + j;
        Sn[r * 65 + c] *= rTr;
        P[r * 65 + c] = (r == c) ? 1.0f : 0.0f;
    }
    __syncthreads();

    for (int it = 0; it < NS_T; it++) {
        mm64(T1, P, P);     // P^2
        mm64(T2, T1, P);    // P^3
        mm64(T1, T2, Sn);   // P^3 Sn
        #pragma unroll
        for (int j = 0; j < 16; j++) {
            int idx = r * 65 + cb + j;
            P[idx] = 1.5f * P[idx] - 0.5f * T1[idx];
        }
        __syncthreads();
    }

    const float s = sqrtf(rTr);
    // fold weight into wm; store transposed layout [d][c]
    #pragma unroll
    for (int j = 0; j < 16; j++) {
        int d = cb + j;
        float w2 = P[r * 65 + d] * s * weight[gi * NCH + r];
        g_wmT[gi][d * NCH + r] = w2;
    }
    // beta[c] = bias[c] - weight[c] * s * sum_d P[c][d]*mean[d]
    if (tid < 64) {
        float off = 0.0f;
        for (int d = 0; d < 64; d++) off += P[tid * 65 + d] * mean[d];
        g_beta[gi][tid] = bias[gi * NCH + tid] - weight[gi * NCH + tid] * s * off;
    }
}

// ---------------- phase 3: whitening apply ----------------
// out[c][s] = sum_d wmT[d][c] * x[d][s] + beta[c]
__global__ __launch_bounds__(256) void whiten_kernel(const float* __restrict__ x,
                                                     float* __restrict__ out) {
    __shared__ float wmT_s[NCH][NCH];   // [d][c]
    __shared__ float beta_s[NCH];
    __shared__ float tile[NCH][116];    // [d][s], pad 116 (16B-mult)

    const int gi  = blockIdx.x / NBLK;
    const int blk = blockIdx.x % NBLK;
    const int tid = threadIdx.x;
    const int ig  = tid >> 4;           // output-channel group: rows ig*4..+3
    const int sg  = tid & 15;           // sample group: 7 samples
    const int soff = sg * 7;

    #pragma unroll
    for (int i = 0; i < 16; i++)
        (&wmT_s[0][0])[tid + 256 * i] = g_wmT[gi][tid + 256 * i];
    if (tid < 64) beta_s[tid] = g_beta[gi][tid];
    __syncthreads();

    const float* xg = x + (size_t)gi * NCH * HWX;
    float* og = out + (size_t)gi * NCH * HWX;

    for (int t = blk; t < TILESG; t += NBLK) {
        const int bb = t / CHUNKS;
        const int cs = (t % CHUNKS) * TS;
        const float* base = xg + (size_t)bb * CC * HWX + cs;

        __syncthreads();
        #pragma unroll
        for (int i = 0; i < 7; i++) {
            int idx = tid + 256 * i;
            int c   = idx / 28;
            int s4  = (idx % 28) * 4;
            float4 v = *reinterpret_cast<const float4*>(base + c * HWX + s4);
            *reinterpret_cast<float4*>(&tile[c][s4]) = v;
        }
        __syncthreads();

        float accv[4][7] = {};
        #pragma unroll 2
        for (int d = 0; d < 64; d++) {
            float4 w = *reinterpret_cast<const float4*>(&wmT_s[d][ig * 4]);
            #pragma unroll
            for (int u = 0; u < 7; u++) {
                float xv = tile[d][soff + u];
                accv[0][u] += w.x * xv;
                accv[1][u] += w.y * xv;
                accv[2][u] += w.z * xv;
                accv[3][u] += w.w * xv;
            }
        }

        float* ob = og + (size_t)bb * CC * HWX + cs;
        #pragma unroll
        for (int rr = 0; rr < 4; rr++) {
            int c = ig * 4 + rr;
            float b = beta_s[c];
            #pragma unroll
            for (int u = 0; u < 7; u++)
                ob[c * HWX + soff + u] = accv[rr][u] + b;
        }
    }
}

// ---------------- launch ----------------
extern "C" void kernel_launch(void* const* d_in, const int* in_sizes, int n_in,
                              void* d_out, int out_size) {
    const float* x      = (const float*)d_in[0];
    const float* weight = (const float*)d_in[1];
    const float* bias   = (const float*)d_in[2];
    float* out          = (float*)d_out;

    // opt-in to >48KB dynamic shared for the NS kernel (idempotent host call)
    const int NS_SMEM = (16704 + 16) * 4;
    cudaFuncSetAttribute(ns_kernel, cudaFuncAttributeMaxDynamicSharedMemorySize,
                         NS_SMEM);

    zero_kernel<<<(G * NCH * NCH + 255) / 256, 256>>>();
    cov_kernel<<<G * NBLK, 256>>>(x);
    ns_kernel<<<G, 256, NS_SMEM>>>(weight, bias);
    whiten_kernel<<<G * NBLK, 256>>>(x, out);
}

// round 4
// speedup vs baseline: 1.0030x; 1.0030x over previous
#include <cuda_runtime.h>

// ---------------- problem constants ----------------
#define BB      64          // batch
#define CC      256         // channels
#define HWX     3136        // 56*56
#define G       4           // whitening groups
#define NCH     64          // channels per group
#define MTOT    (BB*HWX)    // 200704 samples per group
#define TS      112         // samples per tile (divides 3136: 28 chunks)
#define CHUNKS  (HWX/TS)    // 28
#define TILESG  (BB*CHUNKS) // 1792 tiles per group
#define NBLK    74          // blocks per group (grid = 296 = 2 per SM)
#define EPSV    1e-5f
#define NS_T    5

// ---------------- device scratch (no allocations allowed) ----------------
__device__ float g_S2[G][NCH][NCH];   // sum of x x^T
__device__ float g_sum[G][NCH];       // sum of x
__device__ float g_wmT[G][NCH*NCH];   // folded whitening matrix, layout [d][c]
__device__ float g_beta[G][NCH];      // folded per-channel offset

// ---------------- zero scratch ----------------
__global__ void zero_kernel() {
    int i = blockIdx.x * blockDim.x + threadIdx.x;
    float* p = &g_S2[0][0][0];
    if (i < G * NCH * NCH) p[i] = 0.0f;
    if (i < G * NCH) (&g_sum[0][0])[i] = 0.0f;
}

// ---------------- phase 1: covariance raw moments ----------------
// grid = G*NBLK, block = 256. Each block: register-resident 4x4 micro-tile of
// the 64x64 S2 accumulator, looped over its share of 112-sample tiles, one
// atomic flush at the end.
__global__ __launch_bounds__(256) void cov_kernel(const float* __restrict__ x) {
    __shared__ float st[TS][68];      // transposed tile [s][c], pad 68 (16B-mult)

    const int gi  = blockIdx.x / NBLK;
    const int blk = blockIdx.x % NBLK;
    const int tid = threadIdx.x;
    const int ig  = tid >> 4;         // 0..15 -> rows ig*4..ig*4+3
    const int jg  = tid & 15;         // 0..15 -> cols jg*4..jg*4+3

    float acc[4][4] = {};
    float sacc[4]   = {0.f, 0.f, 0.f, 0.f};

    const float* xg = x + (size_t)gi * NCH * HWX;

    for (int t = blk; t < TILESG; t += NBLK) {
        const int bb = t / CHUNKS;
        const int cs = (t % CHUNKS) * TS;
        const float* base = xg + (size_t)bb * CC * HWX + cs;

        __syncthreads();   // previous tile fully consumed
        // load 64x112 floats = 1792 float4, 7 per thread, coalesced rows
        #pragma unroll
        for (int i = 0; i < 7; i++) {
            int idx = tid + 256 * i;
            int c   = idx / 28;
            int s4  = (idx % 28) * 4;
            float4 v = *reinterpret_cast<const float4*>(base + c * HWX + s4);
            st[s4 + 0][c] = v.x;
            st[s4 + 1][c] = v.y;
            st[s4 + 2][c] = v.z;
            st[s4 + 3][c] = v.w;
        }
        __syncthreads();

        #pragma unroll 4
        for (int k = 0; k < TS; k++) {
            float4 a = *reinterpret_cast<const float4*>(&st[k][ig * 4]);
            float4 b = *reinterpret_cast<const float4*>(&st[k][jg * 4]);
            float av[4] = {a.x, a.y, a.z, a.w};
            float bv[4] = {b.x, b.y, b.z, b.w};
            #pragma unroll
            for (int r = 0; r < 4; r++)
                #pragma unroll
                for (int q = 0; q < 4; q++)
                    acc[r][q] += av[r] * bv[q];
            if (ig == 0) {            // warp-0 lanes also collect channel sums
                sacc[0] += bv[0]; sacc[1] += bv[1];
                sacc[2] += bv[2]; sacc[3] += bv[3];
            }
        }
    }

    #pragma unroll
    for (int r = 0; r < 4; r++)
        #pragma unroll
        for (int q = 0; q < 4; q++)
            atomicAdd(&g_S2[gi][ig * 4 + r][jg * 4 + q], acc[r][q]);
    if (ig == 0) {
        #pragma unroll
        for (int q = 0; q < 4; q++)
            atomicAdd(&g_sum[gi][jg * 4 + q], sacc[q]);
    }
}

// ---------------- phase 2: Newton-Schulz + folding ----------------
// One block per group, 256 threads, dynamic smem: 4 matrices [64][65] + mean.
__device__ __forceinline__ void mm64(float* O, const float* A, const float* B) {
    const int r  = threadIdx.x >> 2;         // 0..63
    const int cb = (threadIdx.x & 3) << 4;   // 0,16,32,48
    float acc[16] = {};
    for (int k = 0; k < 64; k++) {
        float a = A[r * 65 + k];
        #pragma unroll
        for (int j = 0; j < 16; j++)
            acc[j] += a * B[k * 65 + cb + j];
    }
    #pragma unroll
    for (int j = 0; j < 16; j++)
        O[r * 65 + cb + j] = acc[j];
    __syncthreads();
}

__global__ __launch_bounds__(256) void ns_kernel(const float* __restrict__ weight,
                                                 const float* __restrict__ bias) {
    extern __shared__ float sm[];
    float* Sn   = sm;
    float* P    = sm + 4160;
    float* T1   = sm + 8320;
    float* T2   = sm + 12480;
    float* mean = sm + 16640;    // 64
    float* misc = sm + 16704;    // scalars

    const int gi  = blockIdx.x;
    const int tid = threadIdx.x;
    const int r   = tid >> 2;
    const int cb  = (tid & 3) << 4;

    if (tid < 64) mean[tid] = g_sum[gi][tid] * (1.0f / MTOT);
    __syncthreads();

    // Sigma -> Sn (unscaled for now)
    #pragma unroll
    for (int j = 0; j < 16; j++) {
        int c = cb + j;
        float sig = g_S2[gi][r][c] * (1.0f / MTOT) - mean[r] * mean[c];
        if (r == c) sig += EPSV;
        Sn[r * 65 + c] = sig;
    }
    __syncthreads();

    // trace -> rTr
    if (tid < 32) {
        float ts = Sn[tid * 65 + tid] + Sn[(tid + 32) * 65 + (tid + 32)];
        #pragma unroll
        for (int o = 16; o; o >>= 1) ts += __shfl_xor_sync(0xffffffffu, ts, o);
        if (tid == 0) misc[0] = 1.0f / ts;
    }
    __syncthreads();
    const float rTr = misc[0];

    // Sn *= rTr ; P = I
    #pragma unroll
    for (int j = 0; j < 16; j++) {
        int c = cb + j;
        Sn[r * 65 + c] *= rTr;
        P[r * 65 + c] = (r == c) ? 1.0f : 0.0f;
    }
    __syncthreads();

    for (int it = 0; it < NS_T; it++) {
        mm64(T1, P, P);     // P^2
        mm64(T2, T1, P);    // P^3
        mm64(T1, T2, Sn);   // P^3 Sn
        #pragma unroll
        for (int j = 0; j < 16; j++) {
            int idx = r * 65 + cb + j;
            P[idx] = 1.5f * P[idx] - 0.5f * T1[idx];
        }
        __syncthreads();
    }

    const float s = sqrtf(rTr);
    // fold weight into wm; store transposed layout [d][c]
    #pragma unroll
    for (int j = 0; j < 16; j++) {
        int d = cb + j;
        float w2 = P[r * 65 + d] * s * weight[gi * NCH + r];
        g_wmT[gi][d * NCH + r] = w2;
    }
    // beta[c] = bias[c] - weight[c] * s * sum_d P[c][d]*mean[d]
    if (tid < 64) {
        float off = 0.0f;
        for (int d = 0; d < 64; d++) off += P[tid * 65 + d] * mean[d];
        g_beta[gi][tid] = bias[gi * NCH + tid] - weight[gi * NCH + tid] * s * off;
    }
}

// ---------------- phase 3: whitening apply ----------------
// out[c][s] = sum_d wmT[d][c] * x[d][s] + beta[c]
__global__ __launch_bounds__(256) void whiten_kernel(const float* __restrict__ x,
                                                     float* __restrict__ out) {
    __shared__ float wmT_s[NCH][NCH];   // [d][c]
    __shared__ float beta_s[NCH];
    __shared__ float tile[NCH][116];    // [d][s], pad 116 (16B-mult)

    const int gi  = blockIdx.x / NBLK;
    const int blk = blockIdx.x % NBLK;
    const int tid = threadIdx.x;
    const int ig  = tid >> 4;           // output-channel group: rows ig*4..+3
    const int sg  = tid & 15;           // sample group: 7 samples
    const int soff = sg * 7;

    #pragma unroll
    for (int i = 0; i < 16; i++)
        (&wmT_s[0][0])[tid + 256 * i] = g_wmT[gi][tid + 256 * i];
    if (tid < 64) beta_s[tid] = g_beta[gi][tid];
    __syncthreads();

    const float* xg = x + (size_t)gi * NCH * HWX;
    float* og = out + (size_t)gi * NCH * HWX;

    for (int t = blk; t < TILESG; t += NBLK) {
        const int bb = t / CHUNKS;
        const int cs = (t % CHUNKS) * TS;
        const float* base = xg + (size_t)bb * CC * HWX + cs;

        __syncthreads();
        #pragma unroll
        for (int i = 0; i < 7; i++) {
            int idx = tid + 256 * i;
            int c   = idx / 28;
            int s4  = (idx % 28) * 4;
            float4 v = *reinterpret_cast<const float4*>(base + c * HWX + s4);
            *reinterpret_cast<float4*>(&tile[c][s4]) = v;
        }
        __syncthreads();

        float accv[4][7] = {};
        #pragma unroll 2
        for (int d = 0; d < 64; d++) {
            float4 w = *reinterpret_cast<const float4*>(&wmT_s[d][ig * 4]);
            #pragma unroll
            for (int u = 0; u < 7; u++) {
                float xv = tile[d][soff + u];
                accv[0][u] += w.x * xv;
                accv[1][u] += w.y * xv;
                accv[2][u] += w.z * xv;
                accv[3][u] += w.w * xv;
            }
        }

        float* ob = og + (size_t)bb * CC * HWX + cs;
        #pragma unroll
        for (int rr = 0; rr < 4; rr++) {
            int c = ig * 4 + rr;
            float b = beta_s[c];
            #pragma unroll
            for (int u = 0; u < 7; u++)
                ob[c * HWX + soff + u] = accv[rr][u] + b;
        }
    }
}

// ---------------- launch ----------------
extern "C" void kernel_launch(void* const* d_in, const int* in_sizes, int n_in,
                              void* d_out, int out_size) {
    const float* x      = (const float*)d_in[0];
    const float* weight = (const float*)d_in[1];
    const float* bias   = (const float*)d_in[2];
    float* out          = (float*)d_out;

    // opt-in to >48KB dynamic shared for the NS kernel (idempotent host call)
    const int NS_SMEM = (16704 + 16) * 4;
    cudaFuncSetAttribute(ns_kernel, cudaFuncAttributeMaxDynamicSharedMemorySize,
                         NS_SMEM);

    zero_kernel<<<(G * NCH * NCH + 255) / 256, 256>>>();
    cov_kernel<<<G * NBLK, 256>>>(x);
    ns_kernel<<<G, 256, NS_SMEM>>>(weight, bias);
    whiten_kernel<<<G * NBLK, 256>>>(x, out);
}